// round 1
// baseline (speedup 1.0000x reference)
#include <cuda_runtime.h>
#include <math.h>

#define BB 32
#define NN 8192
#define NC 256
#define NP 32

// ---------------- scratch (device globals; no allocation allowed) ----------
__device__ float    g_centers[BB * NC * 3];
__device__ float    g_local  [BB * NC * NP * 3];
__device__ float    g_cmean  [BB * NC * 3];
__device__ unsigned g_scale_bits;

// ============================================================================
// K1: Farthest Point Sampling — one block per batch, points + mind in smem.
// Arithmetic replicates the JAX reference exactly (no FMA contraction,
// ((dx*dx+dy*dy)+dz*dz) order, argmax = first max index).
// ============================================================================
__global__ __launch_bounds__(1024, 1)
void fps_kernel(const float* __restrict__ data)
{
    extern __shared__ float sm[];
    float* sx   = sm;
    float* sy   = sm + NN;
    float* sz   = sm + 2 * NN;
    float* mind = sm + 3 * NN;
    __shared__ float rv[32];
    __shared__ int   ri[32];
    __shared__ int   s_sel;

    const int b = blockIdx.x;
    const int t = threadIdx.x;
    if (b == 0 && t == 0) g_scale_bits = 0u;   // reset every launch (graph replay safe)

    const float* dp = data + (size_t)b * 3 * NN;
    for (int n = t; n < NN; n += 1024) {
        sx[n] = dp[n];
        sy[n] = dp[NN + n];
        sz[n] = dp[2 * NN + n];
        mind[n] = 3.4e38f;
    }
    __syncthreads();

    float px = sx[0], py = sy[0], pz = sz[0];
    if (t == 0) {
        float* c = g_centers + (size_t)(b * NC) * 3;
        c[0] = px; c[1] = py; c[2] = pz;
    }

    for (int i = 1; i < NC; i++) {
        // update mind with previous center, track running argmax (first index on tie)
        float bv = -1.0f; int bi = 0;
        for (int n = t; n < NN; n += 1024) {
            float dx = __fadd_rn(sx[n], -px);
            float dy = __fadd_rn(sy[n], -py);
            float dz = __fadd_rn(sz[n], -pz);
            float d  = __fadd_rn(__fadd_rn(__fmul_rn(dx, dx), __fmul_rn(dy, dy)),
                                 __fmul_rn(dz, dz));
            float mo = mind[n];
            float m  = fminf(mo, d);
            mind[n] = m;
            if (m > bv) { bv = m; bi = n; }
        }
        // warp reduce (max val, min idx on tie)
        #pragma unroll
        for (int off = 16; off; off >>= 1) {
            float ov = __shfl_down_sync(0xFFFFFFFFu, bv, off);
            int   oi = __shfl_down_sync(0xFFFFFFFFu, bi, off);
            if (ov > bv || (ov == bv && oi < bi)) { bv = ov; bi = oi; }
        }
        if ((t & 31) == 0) { rv[t >> 5] = bv; ri[t >> 5] = bi; }
        __syncthreads();
        if (t < 32) {
            bv = rv[t]; bi = ri[t];
            #pragma unroll
            for (int off = 16; off; off >>= 1) {
                float ov = __shfl_down_sync(0xFFFFFFFFu, bv, off);
                int   oi = __shfl_down_sync(0xFFFFFFFFu, bi, off);
                if (ov > bv || (ov == bv && oi < bi)) { bv = ov; bi = oi; }
            }
            if (t == 0) {
                s_sel = bi;
                float* c = g_centers + (size_t)(b * NC + i) * 3;
                c[0] = sx[bi]; c[1] = sy[bi]; c[2] = sz[bi];
            }
        }
        __syncthreads();
        int sel = s_sel;
        px = sx[sel]; py = sy[sel]; pz = sz[sel];
    }
}

// ============================================================================
// K2: kNN (set of 32 nearest) — one warp per center, insertion-select.
// Set order is irrelevant downstream; ties prefer lower point index.
// Also computes per-patch mean, un-normalized local coords, and the global
// max squared-norm via atomicMax on float bits.
// ============================================================================
__global__ __launch_bounds__(256)
void knn_kernel(const float* __restrict__ data, const int* __restrict__ perm)
{
    const int w    = (blockIdx.x * blockDim.x + threadIdx.x) >> 5;  // center id 0..8191
    const int lane = threadIdx.x & 31;
    const int b  = w >> 8;
    const int ci = w & 255;
    const int p  = perm[ci];

    const float* cc = g_centers + (size_t)(b * NC + p) * 3;
    const float cx = cc[0], cy = cc[1], cz = cc[2];
    const float cs = (cx * cx + cy * cy) + cz * cz;

    const float* dp = data + (size_t)b * 3 * NN;

    // init set with first 32 points
    float px = dp[lane], py = dp[NN + lane], pz = dp[2 * NN + lane];
    float ps  = (px * px + py * py) + pz * pz;
    float dot = (cx * px + cy * py) + cz * pz;
    float kd  = (cs + ps) - 2.0f * dot;
    int   ki  = lane;
    float cm = kd;
    #pragma unroll
    for (int off = 16; off; off >>= 1) cm = fmaxf(cm, __shfl_xor_sync(0xFFFFFFFFu, cm, off));

    for (int base = 32; base < NN; base += 32) {
        const int n = base + lane;
        px = dp[n]; py = dp[NN + n]; pz = dp[2 * NN + n];
        ps  = (px * px + py * py) + pz * pz;
        dot = (cx * px + cy * py) + cz * pz;
        const float d = (cs + ps) - 2.0f * dot;

        unsigned m = __ballot_sync(0xFFFFFFFFu, d < cm);
        while (m) {
            const int src = __ffs(m) - 1; m &= m - 1;
            const float dc = __shfl_sync(0xFFFFFFFFu, d, src);
            if (dc < cm) {                       // strict: equal keeps lower index
                // argmax of set (tie -> larger original index gets evicted)
                float mv = kd; int mi = ki, ml = lane;
                #pragma unroll
                for (int off = 16; off; off >>= 1) {
                    float ov = __shfl_down_sync(0xFFFFFFFFu, mv, off);
                    int   oi = __shfl_down_sync(0xFFFFFFFFu, mi, off);
                    int   ol = __shfl_down_sync(0xFFFFFFFFu, ml, off);
                    if (ov > mv || (ov == mv && oi > mi)) { mv = ov; mi = oi; ml = ol; }
                }
                ml = __shfl_sync(0xFFFFFFFFu, ml, 0);
                if (lane == ml) { kd = dc; ki = base + src; }
                float q = kd;
                #pragma unroll
                for (int off = 16; off; off >>= 1) q = fmaxf(q, __shfl_xor_sync(0xFFFFFFFFu, q, off));
                cm = q;
            }
        }
    }

    // gather, mean, local coords, global scale
    const float nx = dp[ki], ny = dp[NN + ki], nz = dp[2 * NN + ki];
    float sxx = nx, syy = ny, szz = nz;
    #pragma unroll
    for (int off = 16; off; off >>= 1) {
        sxx += __shfl_xor_sync(0xFFFFFFFFu, sxx, off);
        syy += __shfl_xor_sync(0xFFFFFFFFu, syy, off);
        szz += __shfl_xor_sync(0xFFFFFFFFu, szz, off);
    }
    const float mx = sxx * (1.0f / 32.0f);
    const float my = syy * (1.0f / 32.0f);
    const float mz = szz * (1.0f / 32.0f);
    const float lx = nx - mx, ly = ny - my, lz = nz - mz;
    const float ns = (lx * lx + ly * ly) + lz * lz;
    float wm = ns;
    #pragma unroll
    for (int off = 16; off; off >>= 1) wm = fmaxf(wm, __shfl_xor_sync(0xFFFFFFFFu, wm, off));
    if (lane == 0) atomicMax(&g_scale_bits, __float_as_uint(wm));

    float* lp = g_local + ((size_t)w * NP + lane) * 3;
    lp[0] = lx; lp[1] = ly; lp[2] = lz;
    if (lane < 3) g_cmean[(size_t)w * 3 + lane] = (lane == 0) ? mx : ((lane == 1) ? my : mz);
}

// ============================================================================
// K4: full encoder + 2-stage folding decoder, one block per patch (M=8192).
// Key trick: code @ Wf1a / code @ Wf2a computed once per patch (codeword is
// identical across the 32 rows) -> 2.2x FLOP reduction vs naive.
// ============================================================================
__global__ __launch_bounds__(256, 2)
void mlp_kernel(const float* __restrict__ grid_,
                const float* __restrict__ We1,  const float* __restrict__ be1,
                const float* __restrict__ We2,  const float* __restrict__ be2,
                const float* __restrict__ Wf1a, const float* __restrict__ bf1a,
                const float* __restrict__ Wf1b, const float* __restrict__ bf1b,
                const float* __restrict__ Wf1c, const float* __restrict__ bf1c,
                const float* __restrict__ Wf2a, const float* __restrict__ bf2a,
                const float* __restrict__ Wf2b, const float* __restrict__ bf2b,
                const float* __restrict__ Wf2c, const float* __restrict__ bf2c,
                float* __restrict__ out)
{
    extern __shared__ float s[];
    float* h1T   = s;            // [128][32]        4096
    float* hfT   = s + 4096;     // [256][32]        8192
    float* hf2T  = s + 12288;    // [128][33]        4224
    float* code  = s + 16512;    // [256]
    float* codep = s + 16768;    // [4][256]
    float* base1 = s + 17792;    // [256]
    float* base2 = s + 18048;    // [256]
    float* wgA   = s + 18304;    // [2][256]
    float* wfA   = s + 18816;    // [3][256]
    float* xs    = s + 19584;    // [32][3]
    float* gx    = s + 19680;    // [32]
    float* gy    = s + 19712;    // [32]
    float* fv    = s + 19744;    // [32][3]
    float* cmv   = s + 19840;    // [3]

    const int t = threadIdx.x;
    const int m = blockIdx.x;
    const float scale = sqrtf(__uint_as_float(g_scale_bits));

    if (t < 96) xs[t] = g_local[(size_t)m * 96 + t] / scale;
    if (t < 32) { gx[t] = grid_[2 * t]; gy[t] = grid_[2 * t + 1]; }
    if (t < 3)  cmv[t] = g_cmean[(size_t)m * 3 + t];
    __syncthreads();

    // ---- enc1: h1 = relu(x @ We1[3,128] + be1), stored transposed [c][r] ----
    #pragma unroll
    for (int i = 0; i < 16; i++) {
        const int o = t + 256 * i;
        const int c = o >> 5, r = o & 31;
        float v = xs[r * 3] * We1[c] + xs[r * 3 + 1] * We1[128 + c]
                + xs[r * 3 + 2] * We1[256 + c] + be1[c];
        h1T[c * 32 + r] = fmaxf(v, 0.0f);
    }
    __syncthreads();

    // ---- enc2 + column max: code[c] = max_r relu(h1 @ We2 + be2) ----
    {
        const int cx = t & 63, rx = t >> 6;
        const int c0 = cx * 4, r0 = rx * 8;
        float acc[8][4];
        #pragma unroll
        for (int i = 0; i < 8; i++)
            #pragma unroll
            for (int j = 0; j < 4; j++) acc[i][j] = 0.0f;
        #pragma unroll 2
        for (int k = 0; k < 128; k++) {
            const float4 wv = *(const float4*)(We2 + k * 256 + c0);
            const float4 a0 = *(const float4*)(h1T + k * 32 + r0);
            const float4 a1 = *(const float4*)(h1T + k * 32 + r0 + 4);
            const float av[8] = {a0.x, a0.y, a0.z, a0.w, a1.x, a1.y, a1.z, a1.w};
            #pragma unroll
            for (int i = 0; i < 8; i++) {
                acc[i][0] += av[i] * wv.x;
                acc[i][1] += av[i] * wv.y;
                acc[i][2] += av[i] * wv.z;
                acc[i][3] += av[i] * wv.w;
            }
        }
        #pragma unroll
        for (int j = 0; j < 4; j++) {
            const float bb = be2[c0 + j];
            float mj = 0.0f;                       // relu outputs are >= 0
            #pragma unroll
            for (int i = 0; i < 8; i++) mj = fmaxf(mj, fmaxf(acc[i][j] + bb, 0.0f));
            codep[rx * 256 + c0 + j] = mj;
        }
    }
    __syncthreads();
    code[t] = fmaxf(fmaxf(codep[t], codep[256 + t]), fmaxf(codep[512 + t], codep[768 + t]));
    __syncthreads();

    // ---- fold1 shared part: base1[c] = code . Wf1a[0:256, c] + bf1a[c] ----
    {
        float acc = bf1a[t];
        #pragma unroll 4
        for (int k = 0; k < 256; k++) acc += code[k] * Wf1a[k * 256 + t];
        base1[t] = acc;
        wgA[t]       = Wf1a[256 * 256 + t];
        wgA[256 + t] = Wf1a[257 * 256 + t];
    }
    __syncthreads();

    // ---- hf1T[c][r] = relu(base1[c] + grid terms) ----
    #pragma unroll
    for (int i = 0; i < 32; i++) {
        const int o = t + 256 * i;
        const int c = o >> 5, r = o & 31;
        float v = base1[c] + gx[r] * wgA[c] + gy[r] * wgA[256 + c];
        hfT[c * 32 + r] = fmaxf(v, 0.0f);
    }
    __syncthreads();

    // ---- fold1b: [32,256] @ Wf1b[256,128] + relu -> hf2T[c][r] (stride 33) ----
    {
        const int cx = t & 31, rx = t >> 5;
        const int c0 = cx * 4, r0 = rx * 4;
        float acc[4][4];
        #pragma unroll
        for (int i = 0; i < 4; i++)
            #pragma unroll
            for (int j = 0; j < 4; j++) acc[i][j] = 0.0f;
        #pragma unroll 2
        for (int k = 0; k < 256; k++) {
            const float4 wv = *(const float4*)(Wf1b + k * 128 + c0);
            const float4 a  = *(const float4*)(hfT + k * 32 + r0);
            const float av[4] = {a.x, a.y, a.z, a.w};
            #pragma unroll
            for (int i = 0; i < 4; i++) {
                acc[i][0] += av[i] * wv.x;
                acc[i][1] += av[i] * wv.y;
                acc[i][2] += av[i] * wv.z;
                acc[i][3] += av[i] * wv.w;
            }
        }
        #pragma unroll
        for (int j = 0; j < 4; j++) {
            const float bb = bf1b[c0 + j];
            #pragma unroll
            for (int i = 0; i < 4; i++)
                hf2T[(c0 + j) * 33 + r0 + i] = fmaxf(acc[i][j] + bb, 0.0f);
        }
    }
    __syncthreads();

    // ---- fold1c: f[32][3] = hf2 @ Wf1c + bf1c ----
    if (t < 96) {
        const int r = t / 3, q = t % 3;
        float acc = bf1c[q];
        #pragma unroll 4
        for (int k = 0; k < 128; k++) acc += hf2T[k * 33 + r] * Wf1c[k * 3 + q];
        fv[r * 3 + q] = acc;
    }
    __syncthreads();

    // ---- fold2 shared part: base2[c] = code . Wf2a[0:256, c] + bf2a[c] ----
    {
        float acc = bf2a[t];
        #pragma unroll 4
        for (int k = 0; k < 256; k++) acc += code[k] * Wf2a[k * 256 + t];
        base2[t] = acc;
        wfA[t]       = Wf2a[256 * 256 + t];
        wfA[256 + t] = Wf2a[257 * 256 + t];
        wfA[512 + t] = Wf2a[258 * 256 + t];
    }
    __syncthreads();

    // ---- hf3T[c][r] = relu(base2[c] + f terms) ----
    #pragma unroll
    for (int i = 0; i < 32; i++) {
        const int o = t + 256 * i;
        const int c = o >> 5, r = o & 31;
        float v = base2[c] + fv[r * 3] * wfA[c] + fv[r * 3 + 1] * wfA[256 + c]
                + fv[r * 3 + 2] * wfA[512 + c];
        hfT[c * 32 + r] = fmaxf(v, 0.0f);
    }
    __syncthreads();

    // ---- fold2b: [32,256] @ Wf2b[256,128] + relu ----
    {
        const int cx = t & 31, rx = t >> 5;
        const int c0 = cx * 4, r0 = rx * 4;
        float acc[4][4];
        #pragma unroll
        for (int i = 0; i < 4; i++)
            #pragma unroll
            for (int j = 0; j < 4; j++) acc[i][j] = 0.0f;
        #pragma unroll 2
        for (int k = 0; k < 256; k++) {
            const float4 wv = *(const float4*)(Wf2b + k * 128 + c0);
            const float4 a  = *(const float4*)(hfT + k * 32 + r0);
            const float av[4] = {a.x, a.y, a.z, a.w};
            #pragma unroll
            for (int i = 0; i < 4; i++) {
                acc[i][0] += av[i] * wv.x;
                acc[i][1] += av[i] * wv.y;
                acc[i][2] += av[i] * wv.z;
                acc[i][3] += av[i] * wv.w;
            }
        }
        #pragma unroll
        for (int j = 0; j < 4; j++) {
            const float bb = bf2b[c0 + j];
            #pragma unroll
            for (int i = 0; i < 4; i++)
                hf2T[(c0 + j) * 33 + r0 + i] = fmaxf(acc[i][j] + bb, 0.0f);
        }
    }
    __syncthreads();

    // ---- fold2c + output: out = f2 * scale + cmean ----
    if (t < 96) {
        const int r = t / 3, q = t % 3;
        float acc = bf2c[q];
        #pragma unroll 4
        for (int k = 0; k < 128; k++) acc += hf2T[k * 33 + r] * Wf2c[k * 3 + q];
        out[(size_t)m * 96 + t] = acc * scale + cmv[q];
    }
}

// ============================================================================
extern "C" void kernel_launch(void* const* d_in, const int* in_sizes, int n_in,
                              void* d_out, int out_size)
{
    (void)in_sizes; (void)n_in; (void)out_size;
    const float* data = (const float*)d_in[0];
    const int*   perm = (const int*)  d_in[1];
    const float* grid = (const float*)d_in[2];
    const float* We1  = (const float*)d_in[3];
    const float* be1  = (const float*)d_in[4];
    const float* We2  = (const float*)d_in[5];
    const float* be2  = (const float*)d_in[6];
    const float* Wf1a = (const float*)d_in[7];
    const float* bf1a = (const float*)d_in[8];
    const float* Wf1b = (const float*)d_in[9];
    const float* bf1b = (const float*)d_in[10];
    const float* Wf1c = (const float*)d_in[11];
    const float* bf1c = (const float*)d_in[12];
    const float* Wf2a = (const float*)d_in[13];
    const float* bf2a = (const float*)d_in[14];
    const float* Wf2b = (const float*)d_in[15];
    const float* bf2b = (const float*)d_in[16];
    const float* Wf2c = (const float*)d_in[17];
    const float* bf2c = (const float*)d_in[18];
    float* out = (float*)d_out;

    const int fps_smem = 4 * NN * sizeof(float);          // 131072
    const int mlp_smem = 19844 * sizeof(float);           // 79376
    cudaFuncSetAttribute(fps_kernel, cudaFuncAttributeMaxDynamicSharedMemorySize, fps_smem);
    cudaFuncSetAttribute(mlp_kernel, cudaFuncAttributeMaxDynamicSharedMemorySize, mlp_smem);

    fps_kernel<<<BB, 1024, fps_smem>>>(data);
    knn_kernel<<<(BB * NC) / 8, 256>>>(data, perm);
    mlp_kernel<<<BB * NC, 256, mlp_smem>>>(grid, We1, be1, We2, be2,
                                           Wf1a, bf1a, Wf1b, bf1b, Wf1c, bf1c,
                                           Wf2a, bf2a, Wf2b, bf2b, Wf2c, bf2c,
                                           out);
}

// round 2
// speedup vs baseline: 1.2242x; 1.2242x over previous
#include <cuda_runtime.h>
#include <math.h>

#define BB 32
#define NN 8192
#define NC 256
#define NP 32

// ---------------- scratch (device globals; no allocation allowed) ----------
__device__ float    g_centers[BB * NC * 3];
__device__ float    g_local  [BB * NC * NP * 3];
__device__ float    g_cmean  [BB * NC * 3];
__device__ unsigned g_scale_bits;

// ---------------- packed fp32x2 helpers (sm_100+) ---------------------------
__device__ __forceinline__ unsigned long long pack2(float w) {
    unsigned long long r;
    asm("mov.b64 %0, {%1, %1};" : "=l"(r) : "f"(w));
    return r;
}
__device__ __forceinline__ void fma2(unsigned long long& acc,
                                     unsigned long long a, unsigned long long b) {
    asm("fma.rn.f32x2 %0, %1, %2, %0;" : "+l"(acc) : "l"(a), "l"(b));
}
__device__ __forceinline__ float2 unpack2(unsigned long long v) {
    float2 r;
    asm("mov.b64 {%0, %1}, %2;" : "=f"(r.x), "=f"(r.y) : "l"(v));
    return r;
}

// ============================================================================
// K1: Farthest Point Sampling — one block per batch.
// Points + mind live in REGISTERS (8 pts/thread); smem copy kept only for the
// selected-center coordinate broadcast. Block argmax via packed 64-bit key
// (value bits high, NN-1-idx low -> max key == max value, tie -> lower index,
// exactly jnp.argmax semantics) + warp reduce + one smem atomicMax + ONE
// barrier per iteration (ping-pong key slots).
// Distance arithmetic replicates the reference exactly (no FMA contraction).
// ============================================================================
__global__ __launch_bounds__(1024, 1)
void fps_kernel(const float* __restrict__ data)
{
    extern __shared__ float sm[];
    float* sx = sm;
    float* sy = sm + NN;
    float* sz = sm + 2 * NN;
    __shared__ unsigned long long skey[2];

    const int b = blockIdx.x;
    const int t = threadIdx.x;
    if (b == 0 && t == 0) g_scale_bits = 0u;   // reset every launch (graph replay safe)

    const float* dp = data + (size_t)b * 3 * NN;
    for (int n = t; n < NN; n += 1024) {
        sx[n] = dp[n];
        sy[n] = dp[NN + n];
        sz[n] = dp[2 * NN + n];
    }
    if (t < 2) skey[t] = 0ull;
    __syncthreads();

    float rx[8], ry[8], rz[8], md[8];
    const int base = t * 8;
    #pragma unroll
    for (int j = 0; j < 8; j++) {
        rx[j] = sx[base + j];
        ry[j] = sy[base + j];
        rz[j] = sz[base + j];
        md[j] = 3.4e38f;
    }

    float px = sx[0], py = sy[0], pz = sz[0];
    if (t == 0) {
        float* c = g_centers + (size_t)(b * NC) * 3;
        c[0] = px; c[1] = py; c[2] = pz;
    }

    for (int i = 1; i < NC; i++) {
        float bv = -1.0f; int bi = base;
        #pragma unroll
        for (int j = 0; j < 8; j++) {
            float dx = __fadd_rn(rx[j], -px);
            float dy = __fadd_rn(ry[j], -py);
            float dz = __fadd_rn(rz[j], -pz);
            float d  = __fadd_rn(__fadd_rn(__fmul_rn(dx, dx), __fmul_rn(dy, dy)),
                                 __fmul_rn(dz, dz));
            float m  = fminf(md[j], d);
            md[j] = m;
            if (m > bv) { bv = m; bi = base + j; }   // strict: first index on tie
        }
        unsigned long long key =
            ((unsigned long long)__float_as_uint(bv) << 32) | (unsigned)(NN - 1 - bi);
        #pragma unroll
        for (int off = 16; off; off >>= 1) {
            unsigned long long o = __shfl_down_sync(0xFFFFFFFFu, key, off);
            if (o > key) key = o;
        }
        if ((t & 31) == 0) atomicMax(&skey[i & 1], key);
        if (t == 0) skey[(i + 1) & 1] = 0ull;       // reset next slot (unused this iter)
        __syncthreads();
        const unsigned long long kk = skey[i & 1];
        const int sel = NN - 1 - (int)(kk & 0xFFFFFFFFull);
        px = sx[sel]; py = sy[sel]; pz = sz[sel];
        if (t == 0) {
            float* c = g_centers + (size_t)(b * NC + i) * 3;
            c[0] = px; c[1] = py; c[2] = pz;
        }
    }
}

// ============================================================================
// K2: kNN (set of 32 nearest) — one warp per center, 8 centers (same batch)
// per block; points staged in smem once per block (cuts L2 reads 8x).
// Set order irrelevant downstream; ties prefer lower point index.
// ============================================================================
__global__ __launch_bounds__(256, 2)
void knn_kernel(const float* __restrict__ data, const int* __restrict__ perm)
{
    extern __shared__ float sp[];                    // [3*NN]
    const int warp = threadIdx.x >> 5;
    const int lane = threadIdx.x & 31;
    const int w  = blockIdx.x * 8 + warp;            // center id 0..8191
    const int b  = w >> 8;
    const int ci = w & 255;
    const int p  = perm[ci];

    const float* dp = data + (size_t)b * 3 * NN;
    for (int i = threadIdx.x; i < 3 * NN / 4; i += 256)
        ((float4*)sp)[i] = ((const float4*)dp)[i];
    __syncthreads();
    const float* sx = sp, *sy = sp + NN, *sz = sp + 2 * NN;

    const float* cc = g_centers + (size_t)(b * NC + p) * 3;
    const float cx = cc[0], cy = cc[1], cz = cc[2];
    const float cs = (cx * cx + cy * cy) + cz * cz;

    // init set with first 32 points
    float px = sx[lane], py = sy[lane], pz = sz[lane];
    float ps  = (px * px + py * py) + pz * pz;
    float dot = (cx * px + cy * py) + cz * pz;
    float kd  = (cs + ps) - 2.0f * dot;
    int   ki  = lane;
    float cm = kd;
    #pragma unroll
    for (int off = 16; off; off >>= 1) cm = fmaxf(cm, __shfl_xor_sync(0xFFFFFFFFu, cm, off));

    for (int bse = 32; bse < NN; bse += 32) {
        const int n = bse + lane;
        px = sx[n]; py = sy[n]; pz = sz[n];
        ps  = (px * px + py * py) + pz * pz;
        dot = (cx * px + cy * py) + cz * pz;
        const float d = (cs + ps) - 2.0f * dot;

        unsigned m = __ballot_sync(0xFFFFFFFFu, d < cm);
        while (m) {
            const int src = __ffs(m) - 1; m &= m - 1;
            const float dc = __shfl_sync(0xFFFFFFFFu, d, src);
            if (dc < cm) {                       // strict: equal keeps lower index
                // argmax of set (tie -> larger original index gets evicted)
                float mv = kd; int mi = ki, ml = lane;
                #pragma unroll
                for (int off = 16; off; off >>= 1) {
                    float ov = __shfl_down_sync(0xFFFFFFFFu, mv, off);
                    int   oi = __shfl_down_sync(0xFFFFFFFFu, mi, off);
                    int   ol = __shfl_down_sync(0xFFFFFFFFu, ml, off);
                    if (ov > mv || (ov == mv && oi > mi)) { mv = ov; mi = oi; ml = ol; }
                }
                ml = __shfl_sync(0xFFFFFFFFu, ml, 0);
                if (lane == ml) { kd = dc; ki = bse + src; }
                float q = kd;
                #pragma unroll
                for (int off = 16; off; off >>= 1) q = fmaxf(q, __shfl_xor_sync(0xFFFFFFFFu, q, off));
                cm = q;
            }
        }
    }

    // gather, mean, local coords, global scale
    const float nx = sx[ki], ny = sy[ki], nz = sz[ki];
    float sxx = nx, syy = ny, szz = nz;
    #pragma unroll
    for (int off = 16; off; off >>= 1) {
        sxx += __shfl_xor_sync(0xFFFFFFFFu, sxx, off);
        syy += __shfl_xor_sync(0xFFFFFFFFu, syy, off);
        szz += __shfl_xor_sync(0xFFFFFFFFu, szz, off);
    }
    const float mx = sxx * (1.0f / 32.0f);
    const float my = syy * (1.0f / 32.0f);
    const float mz = szz * (1.0f / 32.0f);
    const float lx = nx - mx, ly = ny - my, lz = nz - mz;
    const float ns = (lx * lx + ly * ly) + lz * lz;
    float wm = ns;
    #pragma unroll
    for (int off = 16; off; off >>= 1) wm = fmaxf(wm, __shfl_xor_sync(0xFFFFFFFFu, wm, off));
    if (lane == 0) atomicMax(&g_scale_bits, __float_as_uint(wm));

    float* lp = g_local + ((size_t)w * NP + lane) * 3;
    lp[0] = lx; lp[1] = ly; lp[2] = lz;
    if (lane < 3) g_cmean[(size_t)w * 3 + lane] = (lane == 0) ? mx : ((lane == 1) ? my : mz);
}

// ============================================================================
// K4: full encoder + 2-stage folding decoder, one block per patch (M=8192).
// GEMM inner loops use packed fma.rn.f32x2 (row-pair accumulators: activation
// pairs come pre-packed from LDS.128, only weights need a {w,w} broadcast).
// code @ Wf*a computed once per patch (codeword identical across 32 rows).
// ============================================================================
__global__ __launch_bounds__(256, 2)
void mlp_kernel(const float* __restrict__ grid_,
                const float* __restrict__ We1,  const float* __restrict__ be1,
                const float* __restrict__ We2,  const float* __restrict__ be2,
                const float* __restrict__ Wf1a, const float* __restrict__ bf1a,
                const float* __restrict__ Wf1b, const float* __restrict__ bf1b,
                const float* __restrict__ Wf1c, const float* __restrict__ bf1c,
                const float* __restrict__ Wf2a, const float* __restrict__ bf2a,
                const float* __restrict__ Wf2b, const float* __restrict__ bf2b,
                const float* __restrict__ Wf2c, const float* __restrict__ bf2c,
                float* __restrict__ out)
{
    extern __shared__ float s[];
    float* h1T   = s;            // [128][32]        4096
    float* hfT   = s + 4096;     // [256][32]        8192
    float* hf2T  = s + 12288;    // [128][33]        4224
    float* code  = s + 16512;    // [256]
    float* codep = s + 16768;    // [4][256]
    float* base1 = s + 17792;    // [256]
    float* base2 = s + 18048;    // [256]
    float* wgA   = s + 18304;    // [2][256]
    float* wfA   = s + 18816;    // [3][256]
    float* xs    = s + 19584;    // [32][3]
    float* gx    = s + 19680;    // [32]
    float* gy    = s + 19712;    // [32]
    float* fv    = s + 19744;    // [32][3]
    float* cmv   = s + 19840;    // [3]

    const int t = threadIdx.x;
    const int m = blockIdx.x;
    const float scale = sqrtf(__uint_as_float(g_scale_bits));

    if (t < 96) xs[t] = g_local[(size_t)m * 96 + t] / scale;
    if (t < 32) { gx[t] = grid_[2 * t]; gy[t] = grid_[2 * t + 1]; }
    if (t < 3)  cmv[t] = g_cmean[(size_t)m * 3 + t];
    __syncthreads();

    // ---- enc1: h1 = relu(x @ We1[3,128] + be1), stored transposed [c][r] ----
    #pragma unroll
    for (int i = 0; i < 16; i++) {
        const int o = t + 256 * i;
        const int c = o >> 5, r = o & 31;
        float v = xs[r * 3] * We1[c] + xs[r * 3 + 1] * We1[128 + c]
                + xs[r * 3 + 2] * We1[256 + c] + be1[c];
        h1T[c * 32 + r] = fmaxf(v, 0.0f);
    }
    __syncthreads();

    // ---- enc2 + column max: code[c] = max_r relu(h1 @ We2 + be2) ----
    {
        const int cx = t & 63, rx = t >> 6;
        const int c0 = cx * 4, r0 = rx * 8;
        unsigned long long acc2[4][4];               // [row-pair][col]
        #pragma unroll
        for (int i = 0; i < 4; i++)
            #pragma unroll
            for (int j = 0; j < 4; j++) acc2[i][j] = 0ull;
        #pragma unroll 2
        for (int k = 0; k < 128; k++) {
            const ulonglong2 a0 = *(const ulonglong2*)(h1T + k * 32 + r0);
            const ulonglong2 a1 = *(const ulonglong2*)(h1T + k * 32 + r0 + 4);
            const unsigned long long ap[4] = {a0.x, a0.y, a1.x, a1.y};
            const float4 wv = *(const float4*)(We2 + k * 256 + c0);
            const unsigned long long w2[4] = {pack2(wv.x), pack2(wv.y),
                                              pack2(wv.z), pack2(wv.w)};
            #pragma unroll
            for (int i = 0; i < 4; i++)
                #pragma unroll
                for (int j = 0; j < 4; j++) fma2(acc2[i][j], ap[i], w2[j]);
        }
        #pragma unroll
        for (int j = 0; j < 4; j++) {
            const float bb = be2[c0 + j];
            float mj = 0.0f;                         // relu outputs are >= 0
            #pragma unroll
            for (int i = 0; i < 4; i++) {
                const float2 v = unpack2(acc2[i][j]);
                mj = fmaxf(mj, fmaxf(fmaxf(v.x + bb, 0.0f), fmaxf(v.y + bb, 0.0f)));
            }
            codep[rx * 256 + c0 + j] = mj;
        }
    }
    __syncthreads();
    code[t] = fmaxf(fmaxf(codep[t], codep[256 + t]), fmaxf(codep[512 + t], codep[768 + t]));
    __syncthreads();

    // ---- fold1 shared part: base1[c] = code . Wf1a[0:256, c] + bf1a[c] ----
    {
        float acc = bf1a[t];
        #pragma unroll 4
        for (int k = 0; k < 256; k++) acc += code[k] * Wf1a[k * 256 + t];
        base1[t] = acc;
        wgA[t]       = Wf1a[256 * 256 + t];
        wgA[256 + t] = Wf1a[257 * 256 + t];
    }
    __syncthreads();

    // ---- hf1T[c][r] = relu(base1[c] + grid terms) ----
    #pragma unroll
    for (int i = 0; i < 32; i++) {
        const int o = t + 256 * i;
        const int c = o >> 5, r = o & 31;
        float v = base1[c] + gx[r] * wgA[c] + gy[r] * wgA[256 + c];
        hfT[c * 32 + r] = fmaxf(v, 0.0f);
    }
    __syncthreads();

    // ---- fold1b: [32,256] @ Wf1b[256,128] + relu -> hf2T[c][r] (stride 33) ----
    {
        const int cx = t & 31, rx = t >> 5;
        const int c0 = cx * 4, r0 = rx * 4;
        unsigned long long acc2[2][4];
        #pragma unroll
        for (int i = 0; i < 2; i++)
            #pragma unroll
            for (int j = 0; j < 4; j++) acc2[i][j] = 0ull;
        #pragma unroll 4
        for (int k = 0; k < 256; k++) {
            const ulonglong2 av = *(const ulonglong2*)(hfT + k * 32 + r0);
            const float4 wv = *(const float4*)(Wf1b + k * 128 + c0);
            const unsigned long long w2[4] = {pack2(wv.x), pack2(wv.y),
                                              pack2(wv.z), pack2(wv.w)};
            #pragma unroll
            for (int j = 0; j < 4; j++) { fma2(acc2[0][j], av.x, w2[j]);
                                          fma2(acc2[1][j], av.y, w2[j]); }
        }
        #pragma unroll
        for (int j = 0; j < 4; j++) {
            const float bb = bf1b[c0 + j];
            const float2 v0 = unpack2(acc2[0][j]);
            const float2 v1 = unpack2(acc2[1][j]);
            hf2T[(c0 + j) * 33 + r0 + 0] = fmaxf(v0.x + bb, 0.0f);
            hf2T[(c0 + j) * 33 + r0 + 1] = fmaxf(v0.y + bb, 0.0f);
            hf2T[(c0 + j) * 33 + r0 + 2] = fmaxf(v1.x + bb, 0.0f);
            hf2T[(c0 + j) * 33 + r0 + 3] = fmaxf(v1.y + bb, 0.0f);
        }
    }
    __syncthreads();

    // ---- fold1c: f[32][3] = hf2 @ Wf1c + bf1c ----
    if (t < 96) {
        const int r = t / 3, q = t % 3;
        float acc = bf1c[q];
        #pragma unroll 4
        for (int k = 0; k < 128; k++) acc += hf2T[k * 33 + r] * Wf1c[k * 3 + q];
        fv[r * 3 + q] = acc;
    }
    __syncthreads();

    // ---- fold2 shared part: base2[c] = code . Wf2a[0:256, c] + bf2a[c] ----
    {
        float acc = bf2a[t];
        #pragma unroll 4
        for (int k = 0; k < 256; k++) acc += code[k] * Wf2a[k * 256 + t];
        base2[t] = acc;
        wfA[t]       = Wf2a[256 * 256 + t];
        wfA[256 + t] = Wf2a[257 * 256 + t];
        wfA[512 + t] = Wf2a[258 * 256 + t];
    }
    __syncthreads();

    // ---- hf3T[c][r] = relu(base2[c] + f terms) ----
    #pragma unroll
    for (int i = 0; i < 32; i++) {
        const int o = t + 256 * i;
        const int c = o >> 5, r = o & 31;
        float v = base2[c] + fv[r * 3] * wfA[c] + fv[r * 3 + 1] * wfA[256 + c]
                + fv[r * 3 + 2] * wfA[512 + c];
        hfT[c * 32 + r] = fmaxf(v, 0.0f);
    }
    __syncthreads();

    // ---- fold2b: [32,256] @ Wf2b[256,128] + relu ----
    {
        const int cx = t & 31, rx = t >> 5;
        const int c0 = cx * 4, r0 = rx * 4;
        unsigned long long acc2[2][4];
        #pragma unroll
        for (int i = 0; i < 2; i++)
            #pragma unroll
            for (int j = 0; j < 4; j++) acc2[i][j] = 0ull;
        #pragma unroll 4
        for (int k = 0; k < 256; k++) {
            const ulonglong2 av = *(const ulonglong2*)(hfT + k * 32 + r0);
            const float4 wv = *(const float4*)(Wf2b + k * 128 + c0);
            const unsigned long long w2[4] = {pack2(wv.x), pack2(wv.y),
                                              pack2(wv.z), pack2(wv.w)};
            #pragma unroll
            for (int j = 0; j < 4; j++) { fma2(acc2[0][j], av.x, w2[j]);
                                          fma2(acc2[1][j], av.y, w2[j]); }
        }
        #pragma unroll
        for (int j = 0; j < 4; j++) {
            const float bb = bf2b[c0 + j];
            const float2 v0 = unpack2(acc2[0][j]);
            const float2 v1 = unpack2(acc2[1][j]);
            hf2T[(c0 + j) * 33 + r0 + 0] = fmaxf(v0.x + bb, 0.0f);
            hf2T[(c0 + j) * 33 + r0 + 1] = fmaxf(v0.y + bb, 0.0f);
            hf2T[(c0 + j) * 33 + r0 + 2] = fmaxf(v1.x + bb, 0.0f);
            hf2T[(c0 + j) * 33 + r0 + 3] = fmaxf(v1.y + bb, 0.0f);
        }
    }
    __syncthreads();

    // ---- fold2c + output: out = f2 * scale + cmean ----
    if (t < 96) {
        const int r = t / 3, q = t % 3;
        float acc = bf2c[q];
        #pragma unroll 4
        for (int k = 0; k < 128; k++) acc += hf2T[k * 33 + r] * Wf2c[k * 3 + q];
        out[(size_t)m * 96 + t] = acc * scale + cmv[q];
    }
}

// ============================================================================
extern "C" void kernel_launch(void* const* d_in, const int* in_sizes, int n_in,
                              void* d_out, int out_size)
{
    (void)in_sizes; (void)n_in; (void)out_size;
    const float* data = (const float*)d_in[0];
    const int*   perm = (const int*)  d_in[1];
    const float* grid = (const float*)d_in[2];
    const float* We1  = (const float*)d_in[3];
    const float* be1  = (const float*)d_in[4];
    const float* We2  = (const float*)d_in[5];
    const float* be2  = (const float*)d_in[6];
    const float* Wf1a = (const float*)d_in[7];
    const float* bf1a = (const float*)d_in[8];
    const float* Wf1b = (const float*)d_in[9];
    const float* bf1b = (const float*)d_in[10];
    const float* Wf1c = (const float*)d_in[11];
    const float* bf1c = (const float*)d_in[12];
    const float* Wf2a = (const float*)d_in[13];
    const float* bf2a = (const float*)d_in[14];
    const float* Wf2b = (const float*)d_in[15];
    const float* bf2b = (const float*)d_in[16];
    const float* Wf2c = (const float*)d_in[17];
    const float* bf2c = (const float*)d_in[18];
    float* out = (float*)d_out;

    const int fps_smem = 3 * NN * sizeof(float);          // 98304
    const int knn_smem = 3 * NN * sizeof(float);          // 98304
    const int mlp_smem = 19844 * sizeof(float);           // 79376
    cudaFuncSetAttribute(fps_kernel, cudaFuncAttributeMaxDynamicSharedMemorySize, fps_smem);
    cudaFuncSetAttribute(knn_kernel, cudaFuncAttributeMaxDynamicSharedMemorySize, knn_smem);
    cudaFuncSetAttribute(mlp_kernel, cudaFuncAttributeMaxDynamicSharedMemorySize, mlp_smem);

    fps_kernel<<<BB, 1024, fps_smem>>>(data);
    knn_kernel<<<(BB * NC) / 8, 256, knn_smem>>>(data, perm);
    mlp_kernel<<<BB * NC, 256, mlp_smem>>>(grid, We1, be1, We2, be2,
                                           Wf1a, bf1a, Wf1b, bf1b, Wf1c, bf1c,
                                           Wf2a, bf2a, Wf2b, bf2b, Wf2c, bf2c,
                                           out);
}

// round 3
// speedup vs baseline: 1.7123x; 1.3987x over previous
#include <cuda_runtime.h>
#include <math.h>

#define BB 32
#define NN 8192
#define NC 256
#define NP 32
#define MTOT (BB * NC)          // 8192 patches

// ---------------- scratch (device globals; no allocation allowed) ----------
__device__ float    g_centers[BB * NC * 3];
__device__ float    g_local  [MTOT * NP * 3];
__device__ float    g_cmean  [MTOT * 3];
__device__ unsigned g_scale_bits;
__device__ float    g_codeT [256 * MTOT];      // code transposed [c][m]  (8 MB)
__device__ float    g_base1 [MTOT * 256];      // [m][c]                  (8 MB)
__device__ float    g_base2 [MTOT * 256];      // [m][c]                  (8 MB)

// ---------------- packed fp32x2 helpers (sm_100+) ---------------------------
__device__ __forceinline__ unsigned long long pack2(float w) {
    unsigned long long r;
    asm("mov.b64 %0, {%1, %1};" : "=l"(r) : "f"(w));
    return r;
}
__device__ __forceinline__ void fma2(unsigned long long& acc,
                                     unsigned long long a, unsigned long long b) {
    asm("fma.rn.f32x2 %0, %1, %2, %0;" : "+l"(acc) : "l"(a), "l"(b));
}
__device__ __forceinline__ float2 unpack2(unsigned long long v) {
    float2 r;
    asm("mov.b64 {%0, %1}, %2;" : "=f"(r.x), "=f"(r.y) : "l"(v));
    return r;
}

// ============================================================================
// K1: Farthest Point Sampling — one block per batch, points/mind in registers,
// one barrier per iteration via 64-bit-key atomicMax argmax (exact jnp.argmax
// tie semantics). Distance arithmetic replicates the reference exactly.
// ============================================================================
__global__ __launch_bounds__(1024, 1)
void fps_kernel(const float* __restrict__ data)
{
    extern __shared__ float sm[];
    float* sx = sm;
    float* sy = sm + NN;
    float* sz = sm + 2 * NN;
    __shared__ unsigned long long skey[2];

    const int b = blockIdx.x;
    const int t = threadIdx.x;
    if (b == 0 && t == 0) g_scale_bits = 0u;   // reset every launch (graph replay safe)

    const float* dp = data + (size_t)b * 3 * NN;
    for (int n = t; n < NN; n += 1024) {
        sx[n] = dp[n];
        sy[n] = dp[NN + n];
        sz[n] = dp[2 * NN + n];
    }
    if (t < 2) skey[t] = 0ull;
    __syncthreads();

    float rx[8], ry[8], rz[8], md[8];
    const int base = t * 8;
    #pragma unroll
    for (int j = 0; j < 8; j++) {
        rx[j] = sx[base + j];
        ry[j] = sy[base + j];
        rz[j] = sz[base + j];
        md[j] = 3.4e38f;
    }

    float px = sx[0], py = sy[0], pz = sz[0];
    if (t == 0) {
        float* c = g_centers + (size_t)(b * NC) * 3;
        c[0] = px; c[1] = py; c[2] = pz;
    }

    for (int i = 1; i < NC; i++) {
        float bv = -1.0f; int bi = base;
        #pragma unroll
        for (int j = 0; j < 8; j++) {
            float dx = __fadd_rn(rx[j], -px);
            float dy = __fadd_rn(ry[j], -py);
            float dz = __fadd_rn(rz[j], -pz);
            float d  = __fadd_rn(__fadd_rn(__fmul_rn(dx, dx), __fmul_rn(dy, dy)),
                                 __fmul_rn(dz, dz));
            float m  = fminf(md[j], d);
            md[j] = m;
            if (m > bv) { bv = m; bi = base + j; }
        }
        unsigned long long key =
            ((unsigned long long)__float_as_uint(bv) << 32) | (unsigned)(NN - 1 - bi);
        #pragma unroll
        for (int off = 16; off; off >>= 1) {
            unsigned long long o = __shfl_down_sync(0xFFFFFFFFu, key, off);
            if (o > key) key = o;
        }
        if ((t & 31) == 0) atomicMax(&skey[i & 1], key);
        if (t == 0) skey[(i + 1) & 1] = 0ull;
        __syncthreads();
        const unsigned long long kk = skey[i & 1];
        const int sel = NN - 1 - (int)(kk & 0xFFFFFFFFull);
        px = sx[sel]; py = sy[sel]; pz = sz[sel];
        if (t == 0) {
            float* c = g_centers + (size_t)(b * NC + i) * 3;
            c[0] = px; c[1] = py; c[2] = pz;
        }
    }
}

// ============================================================================
// K2: kNN set of 32 — one warp per center, 8 centers/block, points in smem.
// ============================================================================
__global__ __launch_bounds__(256, 2)
void knn_kernel(const float* __restrict__ data, const int* __restrict__ perm)
{
    extern __shared__ float sp[];                    // [3*NN]
    const int warp = threadIdx.x >> 5;
    const int lane = threadIdx.x & 31;
    const int w  = blockIdx.x * 8 + warp;
    const int b  = w >> 8;
    const int ci = w & 255;
    const int p  = perm[ci];

    const float* dp = data + (size_t)b * 3 * NN;
    for (int i = threadIdx.x; i < 3 * NN / 4; i += 256)
        ((float4*)sp)[i] = ((const float4*)dp)[i];
    __syncthreads();
    const float* sx = sp, *sy = sp + NN, *sz = sp + 2 * NN;

    const float* cc = g_centers + (size_t)(b * NC + p) * 3;
    const float cx = cc[0], cy = cc[1], cz = cc[2];
    const float cs = (cx * cx + cy * cy) + cz * cz;

    float px = sx[lane], py = sy[lane], pz = sz[lane];
    float ps  = (px * px + py * py) + pz * pz;
    float dot = (cx * px + cy * py) + cz * pz;
    float kd  = (cs + ps) - 2.0f * dot;
    int   ki  = lane;
    float cm = kd;
    #pragma unroll
    for (int off = 16; off; off >>= 1) cm = fmaxf(cm, __shfl_xor_sync(0xFFFFFFFFu, cm, off));

    for (int bse = 32; bse < NN; bse += 32) {
        const int n = bse + lane;
        px = sx[n]; py = sy[n]; pz = sz[n];
        ps  = (px * px + py * py) + pz * pz;
        dot = (cx * px + cy * py) + cz * pz;
        const float d = (cs + ps) - 2.0f * dot;

        unsigned m = __ballot_sync(0xFFFFFFFFu, d < cm);
        while (m) {
            const int src = __ffs(m) - 1; m &= m - 1;
            const float dc = __shfl_sync(0xFFFFFFFFu, d, src);
            if (dc < cm) {
                float mv = kd; int mi = ki, ml = lane;
                #pragma unroll
                for (int off = 16; off; off >>= 1) {
                    float ov = __shfl_down_sync(0xFFFFFFFFu, mv, off);
                    int   oi = __shfl_down_sync(0xFFFFFFFFu, mi, off);
                    int   ol = __shfl_down_sync(0xFFFFFFFFu, ml, off);
                    if (ov > mv || (ov == mv && oi > mi)) { mv = ov; mi = oi; ml = ol; }
                }
                ml = __shfl_sync(0xFFFFFFFFu, ml, 0);
                if (lane == ml) { kd = dc; ki = bse + src; }
                float q = kd;
                #pragma unroll
                for (int off = 16; off; off >>= 1) q = fmaxf(q, __shfl_xor_sync(0xFFFFFFFFu, q, off));
                cm = q;
            }
        }
    }

    const float nx = sx[ki], ny = sy[ki], nz = sz[ki];
    float sxx = nx, syy = ny, szz = nz;
    #pragma unroll
    for (int off = 16; off; off >>= 1) {
        sxx += __shfl_xor_sync(0xFFFFFFFFu, sxx, off);
        syy += __shfl_xor_sync(0xFFFFFFFFu, syy, off);
        szz += __shfl_xor_sync(0xFFFFFFFFu, szz, off);
    }
    const float mx = sxx * (1.0f / 32.0f);
    const float my = syy * (1.0f / 32.0f);
    const float mz = szz * (1.0f / 32.0f);
    const float lx = nx - mx, ly = ny - my, lz = nz - mz;
    const float ns = (lx * lx + ly * ly) + lz * lz;
    float wm = ns;
    #pragma unroll
    for (int off = 16; off; off >>= 1) wm = fmaxf(wm, __shfl_xor_sync(0xFFFFFFFFu, wm, off));
    if (lane == 0) atomicMax(&g_scale_bits, __float_as_uint(wm));

    float* lp = g_local + ((size_t)w * NP + lane) * 3;
    lp[0] = lx; lp[1] = ly; lp[2] = lz;
    if (lane < 3) g_cmean[(size_t)w * 3 + lane] = (lane == 0) ? mx : ((lane == 1) ? my : mz);
}

// ============================================================================
// K3a enc: 2 patches/block (64 rows). x -> h1 -> enc2 GEMM (We2 staged in smem
// slices, LDS-only inner loop) -> maxpool -> g_codeT (transposed).
// ============================================================================
__global__ __launch_bounds__(256, 2)
void enc_kernel(const float* __restrict__ We1, const float* __restrict__ be1,
                const float* __restrict__ We2, const float* __restrict__ be2)
{
    extern __shared__ float s[];
    float* h1T   = s;            // [128][64]   8192
    float* stage = s + 8192;     // [32][256]   8192
    float* xs    = s + 16384;    // [64][3]      192
    float* codep = s + 16576;    // [8][256]    2048  -> total 18624 fl = 74496 B

    const int t  = threadIdx.x;
    const int m0 = blockIdx.x * 2;
    const float scale = sqrtf(__uint_as_float(g_scale_bits));

    if (t < 192) xs[t] = g_local[(size_t)blockIdx.x * 192 + t] / scale;
    __syncthreads();

    // enc1: h1T[k][r] = relu(xs[r]·We1[:,k] + be1[k])
    #pragma unroll
    for (int i = 0; i < 32; i++) {
        const int o = i * 256 + t;
        const int k = o >> 6, r = o & 63;
        float v = xs[r * 3] * We1[k] + xs[r * 3 + 1] * We1[128 + k]
                + xs[r * 3 + 2] * We1[256 + k] + be1[k];
        h1T[k * 64 + r] = fmaxf(v, 0.0f);
    }

    // enc2: C[64 r][256 c]; thread tile 8r x 8c; rg=t&7, cg=t>>3
    const int rg = t & 7, cg = t >> 3;
    const int r0 = rg * 8, c0 = cg * 8;
    unsigned long long acc2[4][8];
    #pragma unroll
    for (int i = 0; i < 4; i++)
        #pragma unroll
        for (int j = 0; j < 8; j++) acc2[i][j] = 0ull;

    for (int sl = 0; sl < 4; sl++) {
        __syncthreads();                 // stage free (also orders h1T writes once)
        const float4* src = (const float4*)(We2 + sl * 32 * 256);
        #pragma unroll
        for (int i = 0; i < 8; i++) ((float4*)stage)[t + 256 * i] = src[t + 256 * i];
        __syncthreads();
        #pragma unroll 4
        for (int k = 0; k < 32; k++) {
            const int kk = sl * 32 + k;
            const ulonglong2 a0 = *(const ulonglong2*)(h1T + kk * 64 + r0);
            const ulonglong2 a1 = *(const ulonglong2*)(h1T + kk * 64 + r0 + 4);
            const unsigned long long ap[4] = {a0.x, a0.y, a1.x, a1.y};
            const float4 w0 = *(const float4*)(stage + k * 256 + c0);
            const float4 w1 = *(const float4*)(stage + k * 256 + c0 + 4);
            const unsigned long long wp[8] = {pack2(w0.x), pack2(w0.y), pack2(w0.z), pack2(w0.w),
                                              pack2(w1.x), pack2(w1.y), pack2(w1.z), pack2(w1.w)};
            #pragma unroll
            for (int i = 0; i < 4; i++)
                #pragma unroll
                for (int j = 0; j < 8; j++) fma2(acc2[i][j], ap[i], wp[j]);
        }
    }
    // per-thread max over its 8 rows (all within one patch), then reduce rowgroups
    #pragma unroll
    for (int j = 0; j < 8; j++) {
        const float bb = be2[c0 + j];
        float mj = 0.0f;
        #pragma unroll
        for (int i = 0; i < 4; i++) {
            const float2 v = unpack2(acc2[i][j]);
            mj = fmaxf(mj, fmaxf(fmaxf(v.x + bb, 0.0f), fmaxf(v.y + bb, 0.0f)));
        }
        codep[rg * 256 + c0 + j] = mj;
    }
    __syncthreads();
    {
        const int c = t;
        const float v0 = fmaxf(fmaxf(codep[c], codep[256 + c]),
                               fmaxf(codep[512 + c], codep[768 + c]));
        const float v1 = fmaxf(fmaxf(codep[1024 + c], codep[1280 + c]),
                               fmaxf(codep[1536 + c], codep[1792 + c]));
        *(float2*)(g_codeT + (size_t)c * MTOT + m0) = make_float2(v0, v1);
    }
}

// ============================================================================
// K3b base: base{1,2}[m][c] = code[m]·Wf{1,2}a[:256,c] + b  (M-tile 64, GEMM)
// ============================================================================
__global__ __launch_bounds__(256, 2)
void base_kernel(const float* __restrict__ Wf1a, const float* __restrict__ bf1a,
                 const float* __restrict__ Wf2a, const float* __restrict__ bf2a)
{
    extern __shared__ float s[];
    float* ct    = s;            // [256 k][64 m]  16384
    float* stage = s + 16384;    // [32 k][256 c]   8192  -> 24576 fl = 98304 B

    const int t  = threadIdx.x;
    const int m0 = blockIdx.x * 64;

    for (int i = t; i < 4096; i += 256) {
        const int k = i >> 4, mq = i & 15;
        *(float4*)(ct + k * 64 + mq * 4) =
            *(const float4*)(g_codeT + (size_t)k * MTOT + m0 + mq * 4);
    }

    const int rg = t & 7, cg = t >> 3;
    const int r0 = rg * 8, c0 = cg * 8;

    #pragma unroll
    for (int mat = 0; mat < 2; mat++) {
        const float* W = mat ? Wf2a : Wf1a;
        const float* bv = mat ? bf2a : bf1a;
        float* dst = mat ? g_base2 : g_base1;

        unsigned long long acc2[4][8];
        #pragma unroll
        for (int i = 0; i < 4; i++)
            #pragma unroll
            for (int j = 0; j < 8; j++) acc2[i][j] = 0ull;

        for (int sl = 0; sl < 8; sl++) {
            __syncthreads();
            const float4* src = (const float4*)(W + sl * 32 * 256);
            #pragma unroll
            for (int i = 0; i < 8; i++) ((float4*)stage)[t + 256 * i] = src[t + 256 * i];
            __syncthreads();
            #pragma unroll 4
            for (int k = 0; k < 32; k++) {
                const int kk = sl * 32 + k;
                const ulonglong2 a0 = *(const ulonglong2*)(ct + kk * 64 + r0);
                const ulonglong2 a1 = *(const ulonglong2*)(ct + kk * 64 + r0 + 4);
                const unsigned long long ap[4] = {a0.x, a0.y, a1.x, a1.y};
                const float4 w0 = *(const float4*)(stage + k * 256 + c0);
                const float4 w1 = *(const float4*)(stage + k * 256 + c0 + 4);
                const unsigned long long wp[8] = {pack2(w0.x), pack2(w0.y), pack2(w0.z), pack2(w0.w),
                                                  pack2(w1.x), pack2(w1.y), pack2(w1.z), pack2(w1.w)};
                #pragma unroll
                for (int i = 0; i < 4; i++)
                    #pragma unroll
                    for (int j = 0; j < 8; j++) fma2(acc2[i][j], ap[i], wp[j]);
            }
        }
        #pragma unroll
        for (int i = 0; i < 4; i++) {
            float4 lo0, lo1, hi0, hi1;
            float* l0 = (float*)&lo0; float* l1 = (float*)&lo1;
            float* h0 = (float*)&hi0; float* h1 = (float*)&hi1;
            #pragma unroll
            for (int j = 0; j < 8; j++) {
                const float bb = bv[c0 + j];
                const float2 v = unpack2(acc2[i][j]);
                if (j < 4) { l0[j] = v.x + bb; h0[j] = v.y + bb; }
                else       { l1[j - 4] = v.x + bb; h1[j - 4] = v.y + bb; }
            }
            float* d0 = dst + (size_t)(m0 + r0 + 2 * i) * 256 + c0;
            float* d1 = dst + (size_t)(m0 + r0 + 2 * i + 1) * 256 + c0;
            *(float4*)d0 = lo0; *(float4*)(d0 + 4) = lo1;
            *(float4*)d1 = hi0; *(float4*)(d1 + 4) = hi1;
        }
    }
}

// ============================================================================
// K3c fold: 1 patch/block. hf = relu(base1 + grid terms); fold1b GEMM (Wf1b
// staged); fold1c -> fv; hg = relu(base2 + fv terms); fold2b GEMM; epilogue.
// ============================================================================
__global__ __launch_bounds__(256, 2)
void fold_kernel(const float* __restrict__ grid_,
                 const float* __restrict__ Wf1a,
                 const float* __restrict__ Wf1b, const float* __restrict__ bf1b,
                 const float* __restrict__ Wf1c, const float* __restrict__ bf1c,
                 const float* __restrict__ Wf2a,
                 const float* __restrict__ Wf2b, const float* __restrict__ bf2b,
                 const float* __restrict__ Wf2c, const float* __restrict__ bf2c,
                 float* __restrict__ out)
{
    extern __shared__ float s[];
    float* hfT   = s;            // [256 k][32 r]  8192
    float* hf2T  = s + 8192;     // [128 k][32 r]  4096
    float* stage = s + 12288;    // [32 k][128 c]  4096
    float* b1    = s + 16384;    // [256]
    float* b2    = s + 16640;    // [256]
    float* wg    = s + 16896;    // [2][256]
    float* wf    = s + 17408;    // [3][256]
    float* Wc1   = s + 18176;    // [384]
    float* Wc2   = s + 18560;    // [384]
    float* gx    = s + 18944;    // [32]
    float* gy    = s + 18976;    // [32]
    float* fv    = s + 19008;    // [96]
    float* cm    = s + 19104;    // [4]   -> total 19108 fl = 76432 B

    const int t = threadIdx.x;
    const int m = blockIdx.x;
    const float scale = sqrtf(__uint_as_float(g_scale_bits));

    b1[t] = g_base1[(size_t)m * 256 + t];
    b2[t] = g_base2[(size_t)m * 256 + t];
    wg[t]       = Wf1a[256 * 256 + t];
    wg[256 + t] = Wf1a[257 * 256 + t];
    wf[t]       = Wf2a[256 * 256 + t];
    wf[256 + t] = Wf2a[257 * 256 + t];
    wf[512 + t] = Wf2a[258 * 256 + t];
    for (int i = t; i < 384; i += 256) { Wc1[i] = Wf1c[i]; Wc2[i] = Wf2c[i]; }
    if (t < 32) { gx[t] = grid_[2 * t]; gy[t] = grid_[2 * t + 1]; }
    if (t < 3)  cm[t] = g_cmean[(size_t)m * 3 + t];
    __syncthreads();

    // hf: [256 k][32 r]
    #pragma unroll
    for (int i = 0; i < 32; i++) {
        const int o = i * 256 + t;
        const int k = o >> 5, r = o & 31;
        hfT[k * 32 + r] = fmaxf(b1[k] + gx[r] * wg[k] + gy[r] * wg[256 + k], 0.0f);
    }

    const int rg = t & 7, cg = t >> 3;
    const int r0 = rg * 4, c0 = cg * 4;

    #pragma unroll
    for (int stagei = 0; stagei < 2; stagei++) {
        const float* W  = stagei ? Wf2b : Wf1b;
        const float* bv = stagei ? bf2b : bf1b;

        unsigned long long acc2[2][4];
        #pragma unroll
        for (int i = 0; i < 2; i++)
            #pragma unroll
            for (int j = 0; j < 4; j++) acc2[i][j] = 0ull;

        for (int sl = 0; sl < 8; sl++) {
            __syncthreads();
            const float4* src = (const float4*)(W + sl * 32 * 128);
            #pragma unroll
            for (int i = 0; i < 4; i++) ((float4*)stage)[t + 256 * i] = src[t + 256 * i];
            __syncthreads();
            #pragma unroll 8
            for (int k = 0; k < 32; k++) {
                const int kk = sl * 32 + k;
                const ulonglong2 a = *(const ulonglong2*)(hfT + kk * 32 + r0);
                const float4 w = *(const float4*)(stage + k * 128 + c0);
                const unsigned long long wp[4] = {pack2(w.x), pack2(w.y),
                                                  pack2(w.z), pack2(w.w)};
                #pragma unroll
                for (int j = 0; j < 4; j++) { fma2(acc2[0][j], a.x, wp[j]);
                                              fma2(acc2[1][j], a.y, wp[j]); }
            }
        }
        #pragma unroll
        for (int j = 0; j < 4; j++) {
            const float bb = bv[c0 + j];
            const float2 v0 = unpack2(acc2[0][j]);
            const float2 v1 = unpack2(acc2[1][j]);
            hf2T[(c0 + j) * 32 + r0 + 0] = fmaxf(v0.x + bb, 0.0f);
            hf2T[(c0 + j) * 32 + r0 + 1] = fmaxf(v0.y + bb, 0.0f);
            hf2T[(c0 + j) * 32 + r0 + 2] = fmaxf(v1.x + bb, 0.0f);
            hf2T[(c0 + j) * 32 + r0 + 3] = fmaxf(v1.y + bb, 0.0f);
        }
        __syncthreads();

        if (stagei == 0) {
            // fold1c: fv[r][q] = hf2[r]·Wf1c[:,q] + bf1c[q]
            if (t < 96) {
                const int r = t / 3, q = t - (t / 3) * 3;
                float acc = bf1c[q];
                #pragma unroll 8
                for (int k = 0; k < 128; k++) acc += hf2T[k * 32 + r] * Wc1[k * 3 + q];
                fv[t] = acc;
            }
            __syncthreads();
            // hg: reuse hfT
            #pragma unroll
            for (int i = 0; i < 32; i++) {
                const int o = i * 256 + t;
                const int k = o >> 5, r = o & 31;
                hfT[k * 32 + r] = fmaxf(b2[k] + fv[r * 3] * wf[k]
                                        + fv[r * 3 + 1] * wf[256 + k]
                                        + fv[r * 3 + 2] * wf[512 + k], 0.0f);
            }
            __syncthreads();
        } else {
            // fold2c + output
            if (t < 96) {
                const int r = t / 3, q = t - (t / 3) * 3;
                float acc = bf2c[q];
                #pragma unroll 8
                for (int k = 0; k < 128; k++) acc += hf2T[k * 32 + r] * Wc2[k * 3 + q];
                out[(size_t)m * 96 + t] = acc * scale + cm[q];
            }
        }
    }
}

// ============================================================================
extern "C" void kernel_launch(void* const* d_in, const int* in_sizes, int n_in,
                              void* d_out, int out_size)
{
    (void)in_sizes; (void)n_in; (void)out_size;
    const float* data = (const float*)d_in[0];
    const int*   perm = (const int*)  d_in[1];
    const float* grid = (const float*)d_in[2];
    const float* We1  = (const float*)d_in[3];
    const float* be1  = (const float*)d_in[4];
    const float* We2  = (const float*)d_in[5];
    const float* be2  = (const float*)d_in[6];
    const float* Wf1a = (const float*)d_in[7];
    const float* bf1a = (const float*)d_in[8];
    const float* Wf1b = (const float*)d_in[9];
    const float* bf1b = (const float*)d_in[10];
    const float* Wf1c = (const float*)d_in[11];
    const float* bf1c = (const float*)d_in[12];
    const float* Wf2a = (const float*)d_in[13];
    const float* bf2a = (const float*)d_in[14];
    const float* Wf2b = (const float*)d_in[15];
    const float* bf2b = (const float*)d_in[16];
    const float* Wf2c = (const float*)d_in[17];
    const float* bf2c = (const float*)d_in[18];
    float* out = (float*)d_out;

    const int fps_smem  = 3 * NN * sizeof(float);      // 98304
    const int knn_smem  = 3 * NN * sizeof(float);      // 98304
    const int enc_smem  = 18624 * sizeof(float);       // 74496
    const int base_smem = 24576 * sizeof(float);       // 98304
    const int fold_smem = 19108 * sizeof(float);       // 76432
    cudaFuncSetAttribute(fps_kernel,  cudaFuncAttributeMaxDynamicSharedMemorySize, fps_smem);
    cudaFuncSetAttribute(knn_kernel,  cudaFuncAttributeMaxDynamicSharedMemorySize, knn_smem);
    cudaFuncSetAttribute(enc_kernel,  cudaFuncAttributeMaxDynamicSharedMemorySize, enc_smem);
    cudaFuncSetAttribute(base_kernel, cudaFuncAttributeMaxDynamicSharedMemorySize, base_smem);
    cudaFuncSetAttribute(fold_kernel, cudaFuncAttributeMaxDynamicSharedMemorySize, fold_smem);

    fps_kernel <<<BB, 1024, fps_smem>>>(data);
    knn_kernel <<<(BB * NC) / 8, 256, knn_smem>>>(data, perm);
    enc_kernel <<<MTOT / 2, 256, enc_smem>>>(We1, be1, We2, be2);
    base_kernel<<<MTOT / 64, 256, base_smem>>>(Wf1a, bf1a, Wf2a, bf2a);
    fold_kernel<<<MTOT, 256, fold_smem>>>(grid, Wf1a, Wf1b, bf1b, Wf1c, bf1c,
                                          Wf2a, Wf2b, bf2b, Wf2c, bf2c, out);
}